// round 9
// baseline (speedup 1.0000x reference)
#include <cuda_runtime.h>
#include <math.h>

#define Bt    16
#define St    128
#define Nn    2048
#define Ee    2032
#define Hh    256
#define DINc  256
#define DEc   192
#define DRc   64
#define Lc    12
#define NLEVc 21
#define NCTA  144
#define NTH   512

typedef unsigned long long u64;

// ---------------- device scratch (no dynamic allocation allowed) ------------
__device__ float g_ix[Nn * Hh];
__device__ float g_fx[Nn * Hh];
__device__ float g_ox[Nn * Hh];
__device__ float g_ux[Nn * Hh];
__device__ float g_h [Nn * Hh];
__device__ float g_c [Nn * Hh];
__device__ float g_pool[Bt * 8 * Hh];
__device__ int   g_child_start[Nn + 1];
__device__ int   g_child_list [Ee];
__device__ int   g_level_nodes[Nn];
__device__ int   g_pairA[Nn + 32];
__device__ int   g_pairB[Nn + 32];
__device__ int   g_npairs;
__device__ int   g_done[Nn];
__device__ int   g_cursor[8 * 32];   // one cursor per column-block, padded

// ---------------- helpers ----------------------------------------------------
__device__ __forceinline__ u64 pk2(float a, float b) {
    u64 r; asm("mov.b64 %0,{%1,%2};" : "=l"(r) : "f"(a), "f"(b)); return r;
}
__device__ __forceinline__ u64 dup2(float a) {
    u64 r; asm("mov.b64 %0,{%1,%1};" : "=l"(r) : "f"(a)); return r;
}
__device__ __forceinline__ void fma2(u64& d, u64 a, u64 b) {
    asm("fma.rn.f32x2 %0,%1,%2,%0;" : "+l"(d) : "l"(a), "l"(b));
}
__device__ __forceinline__ float red2(u64 v) {
    float a, b; asm("mov.b64 {%0,%1},%2;" : "=f"(a), "=f"(b) : "l"(v));
    return a + b;
}
__device__ __forceinline__ float lo2(u64 v) {
    float a, b; asm("mov.b64 {%0,%1},%2;" : "=f"(a), "=f"(b) : "l"(v)); return a;
}
__device__ __forceinline__ float hi2(u64 v) {
    float a, b; asm("mov.b64 {%0,%1},%2;" : "=f"(a), "=f"(b) : "l"(v)); return b;
}
__device__ __forceinline__ int ldacq(const int* p) {
    int v; asm volatile("ld.acquire.gpu.global.s32 %0,[%1];" : "=r"(v) : "l"(p) : "memory");
    return v;
}
__device__ __forceinline__ void red_release(int* p) {
    asm volatile("red.release.gpu.global.add.s32 [%0],1;" :: "l"(p) : "memory");
}
__device__ __forceinline__ void waitdone(const int* p) {
    int it = 0;
    while (ldacq(p) != 8) { if (++it > 32) __nanosleep(128); }
}
__device__ __forceinline__ float sigm(float x) { return 1.f / (1.f + __expf(-x)); }

// ---------------- preprocess: child CSR + level lists + pair list -----------
__global__ void __launch_bounds__(512) preprocess_kernel(
    const int* __restrict__ child_idx,
    const int* __restrict__ parent_idx,
    const int* __restrict__ node_height)
{
    __shared__ int s_cnt[Nn];
    __shared__ int s_aux[512];
    __shared__ int s_par[Ee];
    __shared__ int s_lvl[NLEVc + 1];
    __shared__ int s_start[NLEVc + 1];
    __shared__ int s_cntl[NLEVc + 1];
    __shared__ int s_pstart[NLEVc + 1];
    const int t = threadIdx.x;

    for (int i = t; i < Nn; i += 512) { s_cnt[i] = 0; g_done[i] = 0; }
    for (int e = t; e < Ee; e += 512) s_par[e] = parent_idx[e];
    if (t <= NLEVc) s_lvl[t] = 0;
    if (t < 8) g_cursor[t * 32] = 0;
    __syncthreads();

    for (int e = t; e < Ee; e += 512) atomicAdd(&s_cnt[s_par[e]], 1);
    for (int i = t; i < Nn; i += 512) atomicAdd(&s_lvl[node_height[i]], 1);
    __syncthreads();

    int v[4]; int s = 0;
#pragma unroll
    for (int r = 0; r < 4; r++) { v[r] = s_cnt[t * 4 + r]; s += v[r]; }
    s_aux[t] = s;
    __syncthreads();
    for (int off = 1; off < 512; off <<= 1) {
        int x = (t >= off) ? s_aux[t - off] : 0;
        __syncthreads();
        s_aux[t] += x;
        __syncthreads();
    }
    int run = (t == 0) ? 0 : s_aux[t - 1];
#pragma unroll
    for (int r = 0; r < 4; r++) {
        int c = v[r];
        g_child_start[t * 4 + r] = run;
        s_cnt[t * 4 + r] = run;
        run += c;
    }
    if (t == 511) g_child_start[Nn] = run;
    __syncthreads();

    if (t == 0) {
        int acc = 0, pacc = 0;
        for (int l = 0; l < NLEVc; l++) {
            int c = s_lvl[l];
            s_start[l] = acc;
            s_cntl[l] = c;
            s_pstart[l] = pacc;
            s_lvl[l] = acc;          // becomes scatter cursor
            acc += c;
            pacc += (c + 1) >> 1;
        }
        g_npairs = pacc;
    }
    __syncthreads();

    // warp-per-tree child scatter: rank = #earlier same-parent edges in tree
    {
        int w = t >> 5, lane = t & 31;
        if (w < Bt) {
            int e0 = w * (St - 1);
            for (int el = lane; el < St - 1; el += 32) {
                int e = e0 + el;
                int p = s_par[e];
                int rank = 0;
                for (int e2 = e0; e2 < e; ++e2) rank += (s_par[e2] == p) ? 1 : 0;
                g_child_list[s_cnt[p] + rank] = child_idx[e];
            }
        }
    }
    // level-node scatter + same-level pair construction
    for (int i = t; i < Nn; i += 512) {
        int h = node_height[i];
        int pos = atomicAdd(&s_lvl[h], 1);
        g_level_nodes[pos] = i;
        int rel = pos - s_start[h];
        if ((rel & 1) == 0) {
            int pidx = s_pstart[h] + (rel >> 1);
            g_pairA[pidx] = pos;
            g_pairB[pidx] = (rel + 1 < s_cntl[h]) ? pos + 1 : -1;
        }
    }
}

// ---------------- fused embed + input GEMMs: x[2048,256] @ W[256,256] -------
__global__ void __launch_bounds__(256) input_gemm_kernel(
    const int* __restrict__ xs, const int* __restrict__ rels,
    const float* __restrict__ embW, const float* __restrict__ relW,
    const float* __restrict__ Wix, const float* __restrict__ Wfx,
    const float* __restrict__ Wox, const float* __restrict__ Wux,
    const float* __restrict__ bix, const float* __restrict__ bfx,
    int zbase)
{
    __shared__ __align__(16) float As[16][68];
    __shared__ __align__(16) float Bs[16][68];
    __shared__ int s_xs[64], s_rels[64];
    const int mz = blockIdx.z + zbase;
    const float* W  = (mz == 0) ? Wix : (mz == 1) ? Wfx : (mz == 2) ? Wox : Wux;
    const float* bp = (mz == 0) ? bix : (mz == 1) ? bfx : nullptr;
    float* O = (mz == 0) ? g_ix : (mz == 1) ? g_fx : (mz == 2) ? g_ox : g_ux;

    const int t = threadIdx.x;
    const int tx = t & 15, ty = t >> 4;
    const int row0 = blockIdx.y * 64, col0 = blockIdx.x * 64;
    if (t < 64) { s_xs[t] = xs[row0 + t]; s_rels[t] = rels[row0 + t]; }
    __syncthreads();

    u64 acc[4][2] = {};

    for (int kk = 0; kk < 256; kk += 16) {
        {
            int m = t >> 2, kq = (t & 3) * 4;
            int gk = kk + kq;
            float4 a;
            if (gk < DEc) a = *(const float4*)(embW + (size_t)s_xs[m] * DEc + gk);
            else          a = *(const float4*)(relW + (size_t)s_rels[m] * DRc + (gk - DEc));
            As[kq + 0][m] = a.x; As[kq + 1][m] = a.y;
            As[kq + 2][m] = a.z; As[kq + 3][m] = a.w;
            int k = t >> 4, nq = (t & 15) * 4;
            float4 b = *(const float4*)(W + (kk + k) * 256 + col0 + nq);
            *(float4*)&Bs[k][nq] = b;
        }
        __syncthreads();
#pragma unroll
        for (int k = 0; k < 16; k++) {
            float4 a = *(const float4*)&As[k][ty * 4];
            u64 b0 = *(const u64*)&Bs[k][tx * 4];
            u64 b1 = *(const u64*)&Bs[k][tx * 4 + 2];
            u64 d;
            d = dup2(a.x); fma2(acc[0][0], d, b0); fma2(acc[0][1], d, b1);
            d = dup2(a.y); fma2(acc[1][0], d, b0); fma2(acc[1][1], d, b1);
            d = dup2(a.z); fma2(acc[2][0], d, b0); fma2(acc[2][1], d, b1);
            d = dup2(a.w); fma2(acc[3][0], d, b0); fma2(acc[3][1], d, b1);
        }
        __syncthreads();
    }
    int cc0 = col0 + tx * 4;
    float4 bb = make_float4(0.f, 0.f, 0.f, 0.f);
    if (bp) bb = *(const float4*)(bp + cc0);
#pragma unroll
    for (int r = 0; r < 4; r++) {
        int row = row0 + ty * 4 + r;
        float4 o;
        o.x = lo2(acc[r][0]) + bb.x; o.y = hi2(acc[r][0]) + bb.y;
        o.z = lo2(acc[r][1]) + bb.z; o.w = hi2(acc[r][1]) + bb.w;
        *(float4*)(O + row * 256 + cc0) = o;
    }
}

// ---------------- dataflow recurrence: same-level node PAIRS per warp -------
// Shares every SMEM weight read across two nodes -> halves crossbar traffic.
__global__ void __launch_bounds__(NTH) rec_kernel(
    const float* __restrict__ Wih, const float* __restrict__ Woh,
    const float* __restrict__ Wuh, const float* __restrict__ Wfh,
    const float* __restrict__ bih_g, const float* __restrict__ bfh_g)
{
    extern __shared__ __align__(16) float sm[];
    float* Wi = sm;              // each 8192 floats, pair-interleaved over k:
    float* Wo = sm + 8192;       //   W*[k2*64 + lane*2 + s] = W[2*k2+s][cb*32+lane]
    float* Wu = sm + 16384;
    float* Wf = sm + 24576;
    float* hAll = sm + 32768;    // 16 warps x 512 (two h buffers per warp)

    const int t = threadIdx.x;
    const int lane = t & 31, w = t >> 5;
    const int cb = blockIdx.x & 7;
    const int col = cb * 32 + lane;

    for (int p = t; p < 4096; p += NTH) {
        int k2 = p >> 5, j = p & 31;
        int g0 = (2 * k2) * 256 + cb * 32 + j;
        int o = k2 * 64 + j * 2;
        Wi[o] = Wih[g0]; Wi[o + 1] = Wih[g0 + 256];
        Wo[o] = Woh[g0]; Wo[o + 1] = Woh[g0 + 256];
        Wu[o] = Wuh[g0]; Wu[o + 1] = Wuh[g0 + 256];
        Wf[o] = Wfh[g0]; Wf[o + 1] = Wfh[g0 + 256];
    }
    const float bih = bih_g[col];
    const float bfh = bfh_g[col];
    float* hA = hAll + w * 512;
    float* hB = hA + 256;
    const u64* Wi2 = (const u64*)Wi;
    const u64* Wo2 = (const u64*)Wo;
    const u64* Wu2 = (const u64*)Wu;
    const u64* Wf2 = (const u64*)Wf;
    __syncthreads();
    const int npairs = g_npairs;

    for (;;) {
        int pi;
        if (lane == 0) pi = atomicAdd(&g_cursor[cb * 32], 1);
        pi = __shfl_sync(0xffffffffu, pi, 0);
        if (pi >= npairs) break;
        int posA = g_pairA[pi], posB = g_pairB[pi];
        int n0 = g_level_nodes[posA];
        bool has1 = (posB >= 0);
        int n1 = has1 ? g_level_nodes[posB] : 0;
        int a0 = g_child_start[n0];
        int k0 = g_child_start[n0 + 1] - a0;
        int a1 = 0, k1 = 0;
        if (has1) { a1 = g_child_start[n1]; k1 = g_child_start[n1 + 1] - a1; }

        float ix0 = g_ix[n0 * 256 + col];
        float ox0 = g_ox[n0 * 256 + col];
        float ux0 = g_ux[n0 * 256 + col];
        float fx0 = g_fx[n0 * 256 + col];
        float ix1 = 0.f, ox1 = 0.f, ux1 = 0.f, fx1 = 0.f;
        if (has1) {
            ix1 = g_ix[n1 * 256 + col];
            ox1 = g_ox[n1 * 256 + col];
            ux1 = g_ux[n1 * 256 + col];
            fx1 = g_fx[n1 * 256 + col];
        }

        float rs0[8], rs1[8];
#pragma unroll
        for (int q = 0; q < 8; q++) { rs0[q] = 0.f; rs1[q] = 0.f; }
        float fc0 = 0.f, fc1 = 0.f;
        int kmax = (k0 > k1) ? k0 : k1;

        for (int j = 0; j < kmax; j++) {
            bool act0 = (j < k0), act1 = (j < k1);
            float c0v = 0.f, c1v = 0.f;
            if (act0) {
                int ch = g_child_list[a0 + j];
                waitdone(&g_done[ch]);
                const float* hr = g_h + ch * 256;
#pragma unroll
                for (int q = 0; q < 8; q++) {
                    float vv = __ldcg(hr + q * 32 + lane);
                    hA[q * 32 + lane] = vv;
                    rs0[q] += vv;
                }
                c0v = __ldcg(g_c + ch * 256 + col);
            }
            if (act1) {
                int ch = g_child_list[a1 + j];
                waitdone(&g_done[ch]);
                const float* hr = g_h + ch * 256;
#pragma unroll
                for (int q = 0; q < 8; q++) {
                    float vv = __ldcg(hr + q * 32 + lane);
                    hB[q * 32 + lane] = vv;
                    rs1[q] += vv;
                }
                c1v = __ldcg(g_c + ch * 256 + col);
            }
            __syncwarp();
            if (act0 && act1) {
                u64 fA0 = 0, fA1 = 0, fB0 = 0, fB1 = 0;
#pragma unroll 8
                for (int k2 = 0; k2 < 128; k2 += 2) {
                    u64 w0 = Wf2[(k2 + 0) * 32 + lane];
                    u64 w1 = Wf2[(k2 + 1) * 32 + lane];
                    fma2(fA0, *(const u64*)(hA + 2 * k2), w0);
                    fma2(fA1, *(const u64*)(hA + 2 * k2 + 2), w1);
                    fma2(fB0, *(const u64*)(hB + 2 * k2), w0);
                    fma2(fB1, *(const u64*)(hB + 2 * k2 + 2), w1);
                }
                float f0 = sigm(red2(fA0) + red2(fA1) + bfh + fx0);
                fc0 = fmaf(f0, c0v, fc0);
                float f1 = sigm(red2(fB0) + red2(fB1) + bfh + fx1);
                fc1 = fmaf(f1, c1v, fc1);
            } else {
                const float* hx = act0 ? hA : hB;
                u64 q0 = 0, q1 = 0;
#pragma unroll 8
                for (int k2 = 0; k2 < 128; k2 += 2) {
                    fma2(q0, *(const u64*)(hx + 2 * k2), Wf2[(k2 + 0) * 32 + lane]);
                    fma2(q1, *(const u64*)(hx + 2 * k2 + 2), Wf2[(k2 + 1) * 32 + lane]);
                }
                float fd = red2(q0) + red2(q1);
                if (act0) { float f = sigm(fd + bfh + fx0); fc0 = fmaf(f, c0v, fc0); }
                else      { float f = sigm(fd + bfh + fx1); fc1 = fmaf(f, c1v, fc1); }
            }
            __syncwarp();
        }

        // -------- phase B: i/o/u dots on h_sum, joint over the pair --------
        bool int0 = (k0 > 0), int1 = (k1 > 0);
        if (int0) {
#pragma unroll
            for (int q = 0; q < 8; q++) hA[q * 32 + lane] = rs0[q];
        }
        if (int1) {
#pragma unroll
            for (int q = 0; q < 8; q++) hB[q * 32 + lane] = rs1[q];
        }
        __syncwarp();
        float id0 = 0.f, od0 = 0.f, ud0 = 0.f;
        float id1 = 0.f, od1 = 0.f, ud1 = 0.f;
        if (int0 && int1) {
            u64 ia = 0, oa = 0, ua = 0, ib = 0, ob = 0, ub = 0;
#pragma unroll 4
            for (int k2 = 0; k2 < 128; k2++) {
                u64 wi = Wi2[k2 * 32 + lane];
                u64 wo = Wo2[k2 * 32 + lane];
                u64 wu = Wu2[k2 * 32 + lane];
                u64 pa = *(const u64*)(hA + 2 * k2);
                u64 pb = *(const u64*)(hB + 2 * k2);
                fma2(ia, pa, wi); fma2(oa, pa, wo); fma2(ua, pa, wu);
                fma2(ib, pb, wi); fma2(ob, pb, wo); fma2(ub, pb, wu);
            }
            id0 = red2(ia); od0 = red2(oa); ud0 = red2(ua);
            id1 = red2(ib); od1 = red2(ob); ud1 = red2(ub);
        } else if (int0 || int1) {
            const float* hx = int0 ? hA : hB;
            u64 ia = 0, oa = 0, ua = 0;
#pragma unroll 4
            for (int k2 = 0; k2 < 128; k2++) {
                u64 pa = *(const u64*)(hx + 2 * k2);
                fma2(ia, pa, Wi2[k2 * 32 + lane]);
                fma2(oa, pa, Wo2[k2 * 32 + lane]);
                fma2(ua, pa, Wu2[k2 * 32 + lane]);
            }
            if (int0) { id0 = red2(ia); od0 = red2(oa); ud0 = red2(ua); }
            else      { id1 = red2(ia); od1 = red2(oa); ud1 = red2(ua); }
        }
        __syncwarp();

        // -------- finalize + store + release --------
        {
            float ov, cn;
            if (k0 == 0) {
                cn = sigm(ix0 + bih) * tanhf(ux0);
                ov = sigm(ox0);
            } else {
                float iv = sigm(ix0 + id0 + bih);
                ov = sigm(ox0 + od0);
                float uv = tanhf(ux0 + ud0);
                cn = fmaf(iv, uv, fc0);
            }
            __stcg(g_c + n0 * 256 + col, cn);
            __stcg(g_h + n0 * 256 + col, ov * tanhf(cn));
        }
        if (has1) {
            float ov, cn;
            if (k1 == 0) {
                cn = sigm(ix1 + bih) * tanhf(ux1);
                ov = sigm(ox1);
            } else {
                float iv = sigm(ix1 + id1 + bih);
                ov = sigm(ox1 + od1);
                float uv = tanhf(ux1 + ud1);
                cn = fmaf(iv, uv, fc1);
            }
            __stcg(g_c + n1 * 256 + col, cn);
            __stcg(g_h + n1 * 256 + col, ov * tanhf(cn));
        }
        __syncwarp();
        if (lane == 0) {
            red_release(&g_done[n0]);
            if (has1) red_release(&g_done[n1]);
        }
    }
}

// ---------------- parallel 2-stage max-pool + output ------------------------
__global__ void __launch_bounds__(256) pool1_kernel()
{
    int b = blockIdx.x, chn = blockIdx.y, t = threadIdx.x;
    const float* hb = g_h + ((size_t)b * St + chn * 16) * Hh;
    float m = -1e30f;
#pragma unroll
    for (int s2 = 0; s2 < 16; s2++) m = fmaxf(m, hb[s2 * Hh + t]);
    g_pool[(b * 8 + chn) * Hh + t] = m;
}

__global__ void __launch_bounds__(256) pool2_kernel(
    const float* __restrict__ Wout, const float* __restrict__ bout,
    float* __restrict__ out)
{
    __shared__ float pooled[Hh];
    int b = blockIdx.x, t = threadIdx.x;
    float m = -1e30f;
#pragma unroll
    for (int chn = 0; chn < 8; chn++)
        m = fmaxf(m, g_pool[(b * 8 + chn) * Hh + t]);
    pooled[t] = m;
    __syncthreads();
    if (t < Lc) {
        float acc = bout[t];
        for (int k = 0; k < Hh; k++) acc = fmaf(pooled[k], Wout[k * Lc + t], acc);
        out[b * Lc + t] = acc;
    }
}

// ---------------- host-side launch ------------------------------------------
extern "C" void kernel_launch(void* const* d_in, const int* in_sizes, int n_in,
                              void* d_out, int out_size)
{
    int off = (in_sizes[5] == 1) ? 6 : 5;

    const int* xs        = (const int*)d_in[0];
    const int* rels      = (const int*)d_in[1];
    const int* child_idx = (const int*)d_in[2];
    const int* parent_idx= (const int*)d_in[3];
    const int* height    = (const int*)d_in[4];
    const float* embW  = (const float*)d_in[off + 0];
    const float* relW  = (const float*)d_in[off + 1];
    const float* W_ix  = (const float*)d_in[off + 2];
    const float* b_ix  = (const float*)d_in[off + 3];
    const float* W_ih  = (const float*)d_in[off + 4];
    const float* b_ih  = (const float*)d_in[off + 5];
    const float* W_fx  = (const float*)d_in[off + 6];
    const float* b_fx  = (const float*)d_in[off + 7];
    const float* W_fh  = (const float*)d_in[off + 8];
    const float* b_fh  = (const float*)d_in[off + 9];
    const float* W_ox  = (const float*)d_in[off + 10];
    const float* W_oh  = (const float*)d_in[off + 11];
    const float* W_ux  = (const float*)d_in[off + 12];
    const float* W_uh  = (const float*)d_in[off + 13];
    const float* W_out = (const float*)d_in[off + 14];
    const float* b_out = (const float*)d_in[off + 15];

    cudaFuncSetAttribute(rec_kernel,
                         cudaFuncAttributeMaxDynamicSharedMemorySize, 163840);

    preprocess_kernel<<<1, 512>>>(child_idx, parent_idx, height);
    dim3 gg(4, 32, 2);
    input_gemm_kernel<<<gg, 256>>>(xs, rels, embW, relW,
                                   W_ix, W_fx, W_ox, W_ux, b_ix, b_fx, 0);
    input_gemm_kernel<<<gg, 256>>>(xs, rels, embW, relW,
                                   W_ix, W_fx, W_ox, W_ux, b_ix, b_fx, 2);
    rec_kernel<<<NCTA, NTH, 163840>>>(W_ih, W_oh, W_uh, W_fh, b_ih, b_fh);
    pool1_kernel<<<dim3(16, 8), 256>>>();
    pool2_kernel<<<Bt, 256>>>(W_out, b_out, (float*)d_out);
}